// round 8
// baseline (speedup 1.0000x reference)
#include <cuda_runtime.h>
#include <cuda_bf16.h>
#include <cuda_fp16.h>
#include <math.h>
#include <stdint.h>

#define BATCH 8
#define CH    256
#define NPIX  4096

// Packed split formats: u32 = lo16(hi) | lo16(lo)<<16, value ~= hi + lo
static __device__ uint32_t g_wp[3 * CH * CH];                  // packed bf16 wq|wk|wv
static __device__ uint32_t g_xt[(size_t)BATCH * NPIX * CH];    // x^T  [b][n][c] bf16-split
static __device__ uint32_t g_qt[(size_t)BATCH * NPIX * CH];    // Q^T  [b][n][c] bf16-split
static __device__ uint32_t g_kt[(size_t)BATCH * NPIX * CH];    // K^T  [b][n][c] bf16-split
static __device__ uint32_t g_vp[(size_t)BATCH * CH * NPIX];    // V    [b][c][n] fp16-split

__device__ __forceinline__ uint32_t smem_u32(const void* p) {
    uint32_t a;
    asm("{ .reg .u64 t; cvta.to.shared.u64 t, %1; cvt.u32.u64 %0, t; }" : "=r"(a) : "l"(p));
    return a;
}
__device__ __forceinline__ uint32_t pack_split(float v) {         // bf16 hi+lo
    __nv_bfloat16 h = __float2bfloat16(v);
    float r = v - __bfloat162float(h);
    __nv_bfloat16 l = __float2bfloat16(r);
    return (uint32_t)__bfloat16_as_ushort(h) | ((uint32_t)__bfloat16_as_ushort(l) << 16);
}
__device__ __forceinline__ uint32_t pack_split_h(float v) {       // fp16 hi+lo
    __half h = __float2half(v);
    float r = v - __half2float(h);
    __half l = __float2half(r);
    return (uint32_t)__half_as_ushort(h) | ((uint32_t)__half_as_ushort(l) << 16);
}
__device__ __forceinline__ void cp16(uint32_t saddr, const void* g) {
    uint64_t ga;
    asm("cvta.to.global.u64 %0, %1;" : "=l"(ga) : "l"(g));
    asm volatile("cp.async.cg.shared.global [%0], [%1], 16;" :: "r"(saddr), "l"(ga));
}
#define CP_COMMIT() asm volatile("cp.async.commit_group;" ::: "memory")
#define CP_WAIT1()  asm volatile("cp.async.wait_group 1;"  ::: "memory")
#define CP_WAIT0()  asm volatile("cp.async.wait_group 0;"  ::: "memory")
#define LDS64(a, b, addr) \
    asm volatile("ld.shared.v2.u32 {%0,%1}, [%2];" : "=r"(a), "=r"(b) : "r"(addr))
#define LDS32(a, addr) \
    asm volatile("ld.shared.u32 %0, [%1];" : "=r"(a) : "r"(addr))
#define STS32(addr, v) \
    asm volatile("st.shared.u32 [%0], %1;" :: "r"(addr), "r"(v) : "memory")
#define MMAB(d, a, b0, b1)                                                        \
    asm volatile("mma.sync.aligned.m16n8k16.row.col.f32.bf16.bf16.f32 "           \
        "{%0,%1,%2,%3}, {%4,%5,%6,%7}, {%8,%9}, {%0,%1,%2,%3};"                   \
        : "+f"((d)[0]), "+f"((d)[1]), "+f"((d)[2]), "+f"((d)[3])                  \
        : "r"((a)[0]), "r"((a)[1]), "r"((a)[2]), "r"((a)[3]), "r"(b0), "r"(b1))
#define MMAH(d, a, b0, b1)                                                        \
    asm volatile("mma.sync.aligned.m16n8k16.row.col.f32.f16.f16.f32 "             \
        "{%0,%1,%2,%3}, {%4,%5,%6,%7}, {%8,%9}, {%0,%1,%2,%3};"                   \
        : "+f"((d)[0]), "+f"((d)[1]), "+f"((d)[2]), "+f"((d)[3])                  \
        : "r"((a)[0]), "r"((a)[1]), "r"((a)[2]), "r"((a)[3]), "r"(b0), "r"(b1))

// ---------------------------------------------------------------------------
// QKV projection GEMM (R4-proven): D[M,N] = A[M,K]*B[N,K]^T, split-bf16 3-MMA.
// CTA 128x256, BK=32, 8 warps (2x4), warp tile 64x64, 3-stage cp.async.
// MODE: 1 = packed bf16-split out + bias[col]; 2 = packed fp16-split out + bias[row]
// ---------------------------------------------------------------------------
#define BM 128
#define BN 256
#define BK 32
#define A_U32S  (BM * 40)
#define B_U32S  (BN * 40)
#define A_BYTES (A_U32S * 4)
#define BUF_BYTES ((A_U32S + B_U32S) * 4)   // 61440
#define GEMM_SMEM (3 * BUF_BYTES)           // 184320

__device__ __forceinline__ void load_tiles(const uint32_t* __restrict__ Ag, int lda,
                                           const uint32_t* __restrict__ Bg, int ldb,
                                           uint32_t sbase, int tid) {
    #pragma unroll
    for (int i = 0; i < 4; i++) {
        int t = i * 256 + tid;
        int row = t >> 3, q = t & 7;
        cp16(sbase + (uint32_t)(row * 40 + q * 4) * 4, Ag + (size_t)row * lda + q * 4);
    }
    #pragma unroll
    for (int i = 0; i < 8; i++) {
        int t = i * 256 + tid;
        int row = t >> 3, q = t & 7;
        cp16(sbase + A_BYTES + (uint32_t)(row * 40 + q * 4) * 4, Bg + (size_t)row * ldb + q * 4);
    }
}

__device__ __forceinline__ void compute_tile(uint32_t sa, int lane, int wm, int wn,
                                             float (&acc)[4][8][4]) {
    uint32_t sb = sa + A_BYTES;
    #pragma unroll
    for (int ks = 0; ks < 2; ks++) {
        const int kc = ks * 16 + (lane & 3) * 2;
        uint32_t ah[4][4], al[4][4];
        #pragma unroll
        for (int mt = 0; mt < 4; mt++) {
            int r = wm * 64 + mt * 16 + (lane >> 2);
            uint32_t x0, x1, y0, y1, x2, x3, y2, y3;
            LDS64(x0, x1, sa + (uint32_t)(r * 40 + kc) * 4);
            LDS64(y0, y1, sa + (uint32_t)((r + 8) * 40 + kc) * 4);
            LDS64(x2, x3, sa + (uint32_t)(r * 40 + kc + 8) * 4);
            LDS64(y2, y3, sa + (uint32_t)((r + 8) * 40 + kc + 8) * 4);
            ah[mt][0] = __byte_perm(x0, x1, 0x5410); al[mt][0] = __byte_perm(x0, x1, 0x7632);
            ah[mt][1] = __byte_perm(y0, y1, 0x5410); al[mt][1] = __byte_perm(y0, y1, 0x7632);
            ah[mt][2] = __byte_perm(x2, x3, 0x5410); al[mt][2] = __byte_perm(x2, x3, 0x7632);
            ah[mt][3] = __byte_perm(y2, y3, 0x5410); al[mt][3] = __byte_perm(y2, y3, 0x7632);
        }
        #pragma unroll
        for (int nt = 0; nt < 8; nt++) {
            int r = wn * 64 + nt * 8 + (lane >> 2);
            uint32_t u0, u1, u2, u3;
            LDS64(u0, u1, sb + (uint32_t)(r * 40 + kc) * 4);
            LDS64(u2, u3, sb + (uint32_t)(r * 40 + kc + 8) * 4);
            uint32_t bh0 = __byte_perm(u0, u1, 0x5410), bh1 = __byte_perm(u2, u3, 0x5410);
            uint32_t bl0 = __byte_perm(u0, u1, 0x7632), bl1 = __byte_perm(u2, u3, 0x7632);
            #pragma unroll
            for (int mt = 0; mt < 4; mt++) {
                MMAB(acc[mt][nt], ah[mt], bh0, bh1);
                MMAB(acc[mt][nt], ah[mt], bl0, bl1);
                MMAB(acc[mt][nt], al[mt], bh0, bh1);
            }
        }
    }
}

template<int MODE>
__global__ __launch_bounds__(256)
void gemm_kernel(const uint32_t* __restrict__ A, int lda, size_t sA,
                 const uint32_t* __restrict__ B, int ldb, size_t sB,
                 void* __restrict__ Dv, int ldd, size_t sD,
                 const float* __restrict__ bias, int K)
{
    extern __shared__ __align__(16) uint32_t smraw[];
    const uint32_t smbase = smem_u32(smraw);
    const int tid = threadIdx.x;
    const int lane = tid & 31, wid = tid >> 5;
    const int wm = wid >> 2, wn = wid & 3;
    const int z = blockIdx.z;
    const int bm = blockIdx.y * BM, bn = blockIdx.x * BN;

    A += (size_t)z * sA + (size_t)bm * lda;
    B += (size_t)z * sB + (size_t)bn * ldb;

    float acc[4][8][4];
    #pragma unroll
    for (int i = 0; i < 4; i++)
        #pragma unroll
        for (int j = 0; j < 8; j++)
            #pragma unroll
            for (int v = 0; v < 4; v++) acc[i][j][v] = 0.f;

    const int S = K / BK;
    load_tiles(A, lda, B, ldb, smbase, tid);
    CP_COMMIT();
    load_tiles(A + BK, lda, B + BK, ldb, smbase + BUF_BYTES, tid);
    CP_COMMIT();

    #pragma unroll 1
    for (int s = 0; s < S; s++) {
        CP_WAIT1();
        __syncthreads();
        if (s + 2 < S)
            load_tiles(A + (s + 2) * BK, lda, B + (s + 2) * BK, ldb,
                       smbase + (uint32_t)((s + 2) % 3) * BUF_BYTES, tid);
        CP_COMMIT();
        compute_tile(smbase + (uint32_t)(s % 3) * BUF_BYTES, lane, wm, wn, acc);
    }

    #pragma unroll
    for (int nt = 0; nt < 8; nt++) {
        int col = bn + wn * 64 + nt * 8 + (lane & 3) * 2;
        float bc0 = 0.f, bc1 = 0.f;
        if (MODE == 1) { bc0 = bias[col]; bc1 = bias[col + 1]; }
        #pragma unroll
        for (int mt = 0; mt < 4; mt++) {
            int r0 = bm + wm * 64 + mt * 16 + (lane >> 2);
            uint32_t* D = (uint32_t*)Dv + (size_t)z * sD;
            float br0 = bc0, br1 = bc1, br2 = bc0, br3 = bc1;
            if (MODE == 2) {
                float b0 = bias[r0], b8 = bias[r0 + 8];
                br0 = b0; br1 = b0; br2 = b8; br3 = b8;
            }
            uint32_t p0, p1, p2, p3;
            if (MODE == 2) {
                p0 = pack_split_h(acc[mt][nt][0] + br0);
                p1 = pack_split_h(acc[mt][nt][1] + br1);
                p2 = pack_split_h(acc[mt][nt][2] + br2);
                p3 = pack_split_h(acc[mt][nt][3] + br3);
            } else {
                p0 = pack_split(acc[mt][nt][0] + br0);
                p1 = pack_split(acc[mt][nt][1] + br1);
                p2 = pack_split(acc[mt][nt][2] + br2);
                p3 = pack_split(acc[mt][nt][3] + br3);
            }
            *(uint2*)&D[(size_t)r0 * ldd + col] = make_uint2(p0, p1);
            *(uint2*)&D[(size_t)(r0 + 8) * ldd + col] = make_uint2(p2, p3);
        }
    }
}

// ---------------------------------------------------------------------------
// Flash-fused attention: scores (split-bf16 3-MMA) + online softmax + PV
// (split-fp16 2-MMA) in one kernel. CTA = 64 queries, all 256 channels.
// 256 threads, 8 warps (wm 2 x wn 4).
//   S phase: warp tile 32 i x 32 j, acc_s[2][4][4]
//   PV phase: warp tile 32 i x 64 c, acc_o[2][8][4]
// smem: Q persistent 64x256 u32 (stride 264) | K 2-stage 128x32 u32 (stride 40)
//       | V 2-stage 256x32 u32 (stride 40) | P 64x128 fp16 (stride 136 halves)
//       | row-stat arrays
// ---------------------------------------------------------------------------
#define QOFF 0u
#define KOFF 67584u
#define KSTG 20480u
#define VOFF 108544u
#define VSTG 40960u
#define POFF 190464u
#define MOFF 207872u
#define LOFF 208896u
#define FK_SMEM 209920

__global__ __launch_bounds__(256)
void flash_kernel(float* __restrict__ Out)
{
    extern __shared__ __align__(16) uint32_t smraw[];
    const uint32_t sm = smem_u32(smraw);
    const int tid = threadIdx.x, lane = tid & 31, wid = tid >> 5;
    const int wm = wid >> 2, wn = wid & 3;
    const int b = blockIdx.y;
    const int i0 = blockIdx.x * 64;

    const uint32_t* Qg = g_qt + ((size_t)b * NPIX + i0) * CH;
    const uint32_t* Kg = g_kt + (size_t)b * NPIX * CH;
    const uint32_t* Vg = g_vp + (size_t)b * CH * NPIX;

    // Load persistent Q tile: 64 rows x 256 u32, smem stride 264 u32
    #pragma unroll
    for (int t = 0; t < 16; t++) {
        int task = t * 256 + tid;           // 0..4095
        int row = task >> 6, q = task & 63;
        cp16(sm + QOFF + (uint32_t)(row * 264 + q * 4) * 4, Qg + (size_t)row * CH + q * 4);
    }
    CP_COMMIT();

    float acc_o[2][8][4];
    #pragma unroll
    for (int i = 0; i < 2; i++)
        #pragma unroll
        for (int j = 0; j < 8; j++)
            #pragma unroll
            for (int v = 0; v < 4; v++) acc_o[i][j][v] = 0.f;
    float m_r[2][2], l_r[2][2];
    #pragma unroll
    for (int i = 0; i < 2; i++)
        #pragma unroll
        for (int h = 0; h < 2; h++) { m_r[i][h] = -1e30f; l_r[i][h] = 0.f; }

    const int qrow = lane >> 2;             // 0..7
    const int qcol = lane & 3;              // 0..3

    #pragma unroll 1
    for (int jc = 0; jc < NPIX / 128; jc++) {
        // ---------------- S phase: S[64 x 128] over K=256 ----------------
        float acc_s[2][4][4];
        #pragma unroll
        for (int i = 0; i < 2; i++)
            #pragma unroll
            for (int j = 0; j < 4; j++)
                #pragma unroll
                for (int v = 0; v < 4; v++) acc_s[i][j][v] = 0.f;

        // K tile loader lambda-ish via macro loop
        {
            // issue K(jc,0)
            #pragma unroll
            for (int t = 0; t < 4; t++) {
                int task = t * 256 + tid;   // 1024
                int row = task >> 3, q = task & 7;
                cp16(sm + KOFF + (uint32_t)(row * 40 + q * 4) * 4,
                     Kg + ((size_t)(jc * 128 + row)) * CH + 0 * 32 + q * 4);
            }
            CP_COMMIT();
        }
        #pragma unroll 1
        for (int it = 0; it < 8; it++) {
            if (it + 1 < 8) {
                uint32_t dst = sm + KOFF + (uint32_t)((it + 1) & 1) * KSTG;
                #pragma unroll
                for (int t = 0; t < 4; t++) {
                    int task = t * 256 + tid;
                    int row = task >> 3, q = task & 7;
                    cp16(dst + (uint32_t)(row * 40 + q * 4) * 4,
                         Kg + ((size_t)(jc * 128 + row)) * CH + (it + 1) * 32 + q * 4);
                }
                CP_COMMIT();
                CP_WAIT1();
            } else {
                CP_WAIT0();
            }
            __syncthreads();
            uint32_t kb = sm + KOFF + (uint32_t)(it & 1) * KSTG;
            #pragma unroll
            for (int ks = 0; ks < 2; ks++) {
                const int kcq = it * 32 + ks * 16 + qcol * 2;  // Q col (u32)
                const int kck = ks * 16 + qcol * 2;            // K col (u32)
                uint32_t ah[2][4], al[2][4];
                #pragma unroll
                for (int mt = 0; mt < 2; mt++) {
                    int r = wm * 32 + mt * 16 + qrow;
                    uint32_t x0, x1, y0, y1, x2, x3, y2, y3;
                    LDS64(x0, x1, sm + QOFF + (uint32_t)(r * 264 + kcq) * 4);
                    LDS64(y0, y1, sm + QOFF + (uint32_t)((r + 8) * 264 + kcq) * 4);
                    LDS64(x2, x3, sm + QOFF + (uint32_t)(r * 264 + kcq + 8) * 4);
                    LDS64(y2, y3, sm + QOFF + (uint32_t)((r + 8) * 264 + kcq + 8) * 4);
                    ah[mt][0] = __byte_perm(x0, x1, 0x5410); al[mt][0] = __byte_perm(x0, x1, 0x7632);
                    ah[mt][1] = __byte_perm(y0, y1, 0x5410); al[mt][1] = __byte_perm(y0, y1, 0x7632);
                    ah[mt][2] = __byte_perm(x2, x3, 0x5410); al[mt][2] = __byte_perm(x2, x3, 0x7632);
                    ah[mt][3] = __byte_perm(y2, y3, 0x5410); al[mt][3] = __byte_perm(y2, y3, 0x7632);
                }
                #pragma unroll
                for (int nt = 0; nt < 4; nt++) {
                    int r = wn * 32 + nt * 8 + qrow;
                    uint32_t u0, u1, u2, u3;
                    LDS64(u0, u1, kb + (uint32_t)(r * 40 + kck) * 4);
                    LDS64(u2, u3, kb + (uint32_t)(r * 40 + kck + 8) * 4);
                    uint32_t bh0 = __byte_perm(u0, u1, 0x5410), bh1 = __byte_perm(u2, u3, 0x5410);
                    uint32_t bl0 = __byte_perm(u0, u1, 0x7632), bl1 = __byte_perm(u2, u3, 0x7632);
                    #pragma unroll
                    for (int mt = 0; mt < 2; mt++) {
                        MMAB(acc_s[mt][nt], ah[mt], bh0, bh1);
                        MMAB(acc_s[mt][nt], ah[mt], bl0, bl1);
                        MMAB(acc_s[mt][nt], al[mt], bh0, bh1);
                    }
                }
            }
            __syncthreads();
        }

        // issue V(jc,0) early so its latency hides under softmax
        {
            uint32_t dst = sm + VOFF;
            #pragma unroll
            for (int t = 0; t < 8; t++) {
                int task = t * 256 + tid;   // 2048
                int row = task >> 3, q = task & 7;
                cp16(dst + (uint32_t)(row * 40 + q * 4) * 4,
                     Vg + (size_t)row * NPIX + jc * 128 + 0 * 32 + q * 4);
            }
            CP_COMMIT();
        }

        // ---------------- online softmax ----------------
        // chunk row max
        float mx[2][2];
        #pragma unroll
        for (int mt = 0; mt < 2; mt++)
            #pragma unroll
            for (int h = 0; h < 2; h++) {
                float v = -1e30f;
                #pragma unroll
                for (int nt = 0; nt < 4; nt++)
                    v = fmaxf(v, fmaxf(acc_s[mt][nt][h * 2], acc_s[mt][nt][h * 2 + 1]));
                v = fmaxf(v, __shfl_xor_sync(0xffffffffu, v, 1));
                v = fmaxf(v, __shfl_xor_sync(0xffffffffu, v, 2));
                mx[mt][h] = v;
            }
        float* sredm = (float*)(smraw) + (MOFF >> 2);
        float* sredl = (float*)(smraw) + (LOFF >> 2);
        if (qcol == 0) {
            #pragma unroll
            for (int mt = 0; mt < 2; mt++)
                #pragma unroll
                for (int h = 0; h < 2; h++)
                    sredm[wn * 64 + wm * 32 + mt * 16 + qrow + h * 8] = mx[mt][h];
        }
        __syncthreads();
        float mnew[2][2], alpha[2][2];
        #pragma unroll
        for (int mt = 0; mt < 2; mt++)
            #pragma unroll
            for (int h = 0; h < 2; h++) {
                int row = wm * 32 + mt * 16 + qrow + h * 8;
                float cm = fmaxf(fmaxf(sredm[row], sredm[64 + row]),
                                 fmaxf(sredm[128 + row], sredm[192 + row]));
                float mn = fmaxf(m_r[mt][h], cm);
                alpha[mt][h] = __expf(m_r[mt][h] - mn);
                m_r[mt][h] = mn;
                mnew[mt][h] = mn;
            }
        // p = exp(s - m), write P fp16, local row sums
        float ls[2][2] = {{0.f, 0.f}, {0.f, 0.f}};
        #pragma unroll
        for (int mt = 0; mt < 2; mt++)
            #pragma unroll
            for (int h = 0; h < 2; h++) {
                int row = wm * 32 + mt * 16 + qrow + h * 8;
                #pragma unroll
                for (int nt = 0; nt < 4; nt++) {
                    float p0 = __expf(acc_s[mt][nt][h * 2]     - mnew[mt][h]);
                    float p1 = __expf(acc_s[mt][nt][h * 2 + 1] - mnew[mt][h]);
                    ls[mt][h] += p0 + p1;
                    __half2 hp = __floats2half2_rn(p0, p1);
                    int col = wn * 32 + nt * 8 + qcol * 2;   // fp16 col
                    STS32(sm + POFF + (uint32_t)(row * 272 + col * 2),
                          *(uint32_t*)&hp);
                }
            }
        #pragma unroll
        for (int mt = 0; mt < 2; mt++)
            #pragma unroll
            for (int h = 0; h < 2; h++) {
                float v = ls[mt][h];
                v += __shfl_xor_sync(0xffffffffu, v, 1);
                v += __shfl_xor_sync(0xffffffffu, v, 2);
                if (qcol == 0)
                    sredl[wn * 64 + wm * 32 + mt * 16 + qrow + h * 8] = v;
            }
        // scale O while sums land
        #pragma unroll
        for (int mt = 0; mt < 2; mt++)
            #pragma unroll
            for (int nt = 0; nt < 8; nt++) {
                acc_o[mt][nt][0] *= alpha[mt][0];
                acc_o[mt][nt][1] *= alpha[mt][0];
                acc_o[mt][nt][2] *= alpha[mt][1];
                acc_o[mt][nt][3] *= alpha[mt][1];
            }
        __syncthreads();
        #pragma unroll
        for (int mt = 0; mt < 2; mt++)
            #pragma unroll
            for (int h = 0; h < 2; h++) {
                int row = wm * 32 + mt * 16 + qrow + h * 8;
                float cs = sredl[row] + sredl[64 + row] + sredl[128 + row] + sredl[192 + row];
                l_r[mt][h] = l_r[mt][h] * alpha[mt][h] + cs;
            }

        // ---------------- PV phase: O += P[64x128] * V[c][j]^T ----------------
        #pragma unroll 1
        for (int jv = 0; jv < 4; jv++) {
            if (jv + 1 < 4) {
                uint32_t dst = sm + VOFF + (uint32_t)((jv + 1) & 1) * VSTG;
                #pragma unroll
                for (int t = 0; t < 8; t++) {
                    int task = t * 256 + tid;
                    int row = task >> 3, q = task & 7;
                    cp16(dst + (uint32_t)(row * 40 + q * 4) * 4,
                         Vg + (size_t)row * NPIX + jc * 128 + (jv + 1) * 32 + q * 4);
                }
                CP_COMMIT();
                CP_WAIT1();
            } else {
                CP_WAIT0();
            }
            __syncthreads();
            uint32_t vb = sm + VOFF + (uint32_t)(jv & 1) * VSTG;
            #pragma unroll
            for (int kj = 0; kj < 2; kj++) {
                // A = P fragments, rows match O rows
                uint32_t ap[2][4];
                const int pcol = jv * 32 + kj * 16 + qcol * 2;  // fp16 col
                #pragma unroll
                for (int mt = 0; mt < 2; mt++) {
                    int r = wm * 32 + mt * 16 + qrow;
                    LDS32(ap[mt][0], sm + POFF + (uint32_t)(r * 272 + pcol * 2));
                    LDS32(ap[mt][1], sm + POFF + (uint32_t)((r + 8) * 272 + pcol * 2));
                    LDS32(ap[mt][2], sm + POFF + (uint32_t)(r * 272 + (pcol + 8) * 2));
                    LDS32(ap[mt][3], sm + POFF + (uint32_t)((r + 8) * 272 + (pcol + 8) * 2));
                }
                const int kcv = kj * 16 + qcol * 2;
                #pragma unroll
                for (int nt = 0; nt < 8; nt++) {
                    int cr = wn * 64 + nt * 8 + qrow;
                    uint32_t u0, u1, u2, u3;
                    LDS64(u0, u1, vb + (uint32_t)(cr * 40 + kcv) * 4);
                    LDS64(u2, u3, vb + (uint32_t)(cr * 40 + kcv + 8) * 4);
                    uint32_t bh0 = __byte_perm(u0, u1, 0x5410), bh1 = __byte_perm(u2, u3, 0x5410);
                    uint32_t bl0 = __byte_perm(u0, u1, 0x7632), bl1 = __byte_perm(u2, u3, 0x7632);
                    #pragma unroll
                    for (int mt = 0; mt < 2; mt++) {
                        MMAH(acc_o[mt][nt], ap[mt], bh0, bh1);
                        MMAH(acc_o[mt][nt], ap[mt], bl0, bl1);
                    }
                }
            }
            __syncthreads();
        }
    }

    // ---------------- epilogue: O / l -> out[b][c][i] ----------------
    float inv[2][2];
    #pragma unroll
    for (int mt = 0; mt < 2; mt++)
        #pragma unroll
        for (int h = 0; h < 2; h++) inv[mt][h] = 1.0f / l_r[mt][h];

    float* Ob = Out + (size_t)b * CH * NPIX;
    #pragma unroll
    for (int mt = 0; mt < 2; mt++)
        #pragma unroll
        for (int nt = 0; nt < 8; nt++) {
            int c0 = wn * 64 + nt * 8 + qcol * 2;
            int r  = i0 + wm * 32 + mt * 16 + qrow;
            Ob[(size_t)c0 * NPIX + r]           = acc_o[mt][nt][0] * inv[mt][0];
            Ob[(size_t)(c0 + 1) * NPIX + r]     = acc_o[mt][nt][1] * inv[mt][0];
            Ob[(size_t)c0 * NPIX + r + 8]       = acc_o[mt][nt][2] * inv[mt][1];
            Ob[(size_t)(c0 + 1) * NPIX + r + 8] = acc_o[mt][nt][3] * inv[mt][1];
        }
}

// ---------------------------------------------------------------------------
// Packing kernels
// ---------------------------------------------------------------------------
__global__ __launch_bounds__(256) void pack_w_kernel(
    const float* __restrict__ wq, const float* __restrict__ wk,
    const float* __restrict__ wv)
{
    int i = blockIdx.x * 256 + threadIdx.x;
    g_wp[i]               = pack_split(wq[i]);
    g_wp[CH * CH + i]     = pack_split(wk[i]);
    g_wp[2 * CH * CH + i] = pack_split(wv[i]);
}

__global__ __launch_bounds__(256) void pack_xt_kernel(const float* __restrict__ x)
{
    __shared__ float t[32][33];
    const int b = blockIdx.z;
    const int n0 = blockIdx.x * 32, c0 = blockIdx.y * 32;
    const int tx = threadIdx.x, ty = threadIdx.y;   // 32 x 8
    const float* xb = x + (size_t)b * CH * NPIX;
    #pragma unroll
    for (int i = 0; i < 4; i++)
        t[ty * 4 + i][tx] = xb[(size_t)(c0 + ty * 4 + i) * NPIX + n0 + tx];
    __syncthreads();
    uint32_t* xt = g_xt + (size_t)b * NPIX * CH;
    #pragma unroll
    for (int i = 0; i < 4; i++)
        xt[(size_t)(n0 + ty * 4 + i) * CH + c0 + tx] = pack_split(t[tx][ty * 4 + i]);
}

// ---------------------------------------------------------------------------
extern "C" void kernel_launch(void* const* d_in, const int* in_sizes, int n_in,
                              void* d_out, int out_size)
{
    const float* x  = (const float*)d_in[0];
    const float* wq = (const float*)d_in[1];
    const float* bq = (const float*)d_in[2];
    const float* wk = (const float*)d_in[3];
    const float* bk = (const float*)d_in[4];
    const float* wv = (const float*)d_in[5];
    const float* bv = (const float*)d_in[6];
    float* out = (float*)d_out;

    void *pwp, *pxt, *pqt, *pkt, *pvp;
    cudaGetSymbolAddress(&pwp, g_wp);
    cudaGetSymbolAddress(&pxt, g_xt);
    cudaGetSymbolAddress(&pqt, g_qt);
    cudaGetSymbolAddress(&pkt, g_kt);
    cudaGetSymbolAddress(&pvp, g_vp);
    uint32_t* wp = (uint32_t*)pwp;
    uint32_t* xt = (uint32_t*)pxt;
    uint32_t* qt = (uint32_t*)pqt;
    uint32_t* kt = (uint32_t*)pkt;
    uint32_t* vp = (uint32_t*)pvp;

    cudaFuncSetAttribute(gemm_kernel<1>, cudaFuncAttributeMaxDynamicSharedMemorySize, GEMM_SMEM);
    cudaFuncSetAttribute(gemm_kernel<2>, cudaFuncAttributeMaxDynamicSharedMemorySize, GEMM_SMEM);
    cudaFuncSetAttribute(flash_kernel,   cudaFuncAttributeMaxDynamicSharedMemorySize, FK_SMEM);

    pack_w_kernel<<<CH * CH / 256, 256>>>(wq, wk, wv);
    pack_xt_kernel<<<dim3(NPIX / 32, CH / 32, BATCH), dim3(32, 8)>>>(x);

    // Q^T[n][c] = X^T[n][k] * Wq[c][k]^T + bq (col bias)
    gemm_kernel<1><<<dim3(1, 32, BATCH), 256, GEMM_SMEM>>>(
        xt, CH, (size_t)NPIX * CH, wp, CH, 0,
        qt, CH, (size_t)NPIX * CH, bq, CH);
    gemm_kernel<1><<<dim3(1, 32, BATCH), 256, GEMM_SMEM>>>(
        xt, CH, (size_t)NPIX * CH, wp + CH * CH, CH, 0,
        kt, CH, (size_t)NPIX * CH, bk, CH);
    // V[c][n] = Wv[c][k] * X^T[n][k]^T + bv (row bias) -> fp16-split pack
    gemm_kernel<2><<<dim3(NPIX / BN, CH / BM, BATCH), 256, GEMM_SMEM>>>(
        wp + 2 * CH * CH, CH, 0, xt, CH, (size_t)NPIX * CH,
        vp, NPIX, (size_t)CH * NPIX, bv, CH);
    // fused scores + softmax + AV
    flash_kernel<<<dim3(NPIX / 64, BATCH), 256, FK_SMEM>>>(out);
}

// round 9
// speedup vs baseline: 1.4195x; 1.4195x over previous
#include <cuda_runtime.h>
#include <cuda_bf16.h>
#include <cuda_fp16.h>
#include <math.h>
#include <stdint.h>

#define BATCH 8
#define CH    256
#define NPIX  4096

// Packed split formats: u32 = lo16(hi) | lo16(lo)<<16, value ~= hi + lo
static __device__ uint32_t g_wp[3 * CH * CH];                  // packed bf16 wq|wk|wv
static __device__ uint32_t g_xt[(size_t)BATCH * NPIX * CH];    // x^T  [b][n][c] bf16-split
static __device__ uint32_t g_qt[(size_t)BATCH * NPIX * CH];    // Q^T  [b][n][c] bf16-split
static __device__ uint32_t g_kt[(size_t)BATCH * NPIX * CH];    // K^T  [b][n][c] bf16-split
static __device__ __half   g_vh[(size_t)BATCH * CH * NPIX];    // V    [b][c][n] fp16 single
static __device__ float    g_s [(size_t)BATCH * NPIX * NPIX];  // scores fp32
static __device__ __half   g_ah[(size_t)BATCH * NPIX * NPIX];  // attn fp16 [b][i][j]

__device__ __forceinline__ uint32_t smem_u32(const void* p) {
    uint32_t a;
    asm("{ .reg .u64 t; cvta.to.shared.u64 t, %1; cvt.u32.u64 %0, t; }" : "=r"(a) : "l"(p));
    return a;
}
__device__ __forceinline__ uint32_t pack_split(float v) {         // bf16 hi+lo
    __nv_bfloat16 h = __float2bfloat16(v);
    float r = v - __bfloat162float(h);
    __nv_bfloat16 l = __float2bfloat16(r);
    return (uint32_t)__bfloat16_as_ushort(h) | ((uint32_t)__bfloat16_as_ushort(l) << 16);
}
__device__ __forceinline__ void cp16(uint32_t saddr, const void* g) {
    uint64_t ga;
    asm("cvta.to.global.u64 %0, %1;" : "=l"(ga) : "l"(g));
    asm volatile("cp.async.cg.shared.global [%0], [%1], 16;" :: "r"(saddr), "l"(ga));
}
#define CP_COMMIT() asm volatile("cp.async.commit_group;" ::: "memory")
#define CP_WAIT1()  asm volatile("cp.async.wait_group 1;"  ::: "memory")
#define LDS64(a, b, addr) \
    asm volatile("ld.shared.v2.u32 {%0,%1}, [%2];" : "=r"(a), "=r"(b) : "r"(addr))
#define LDS32(a, addr) \
    asm volatile("ld.shared.u32 %0, [%1];" : "=r"(a) : "r"(addr))
#define MMAB(d, a, b0, b1)                                                        \
    asm volatile("mma.sync.aligned.m16n8k16.row.col.f32.bf16.bf16.f32 "           \
        "{%0,%1,%2,%3}, {%4,%5,%6,%7}, {%8,%9}, {%0,%1,%2,%3};"                   \
        : "+f"((d)[0]), "+f"((d)[1]), "+f"((d)[2]), "+f"((d)[3])                  \
        : "r"((a)[0]), "r"((a)[1]), "r"((a)[2]), "r"((a)[3]), "r"(b0), "r"(b1))
#define MMAH(d, a, b0, b1)                                                        \
    asm volatile("mma.sync.aligned.m16n8k16.row.col.f32.f16.f16.f32 "             \
        "{%0,%1,%2,%3}, {%4,%5,%6,%7}, {%8,%9}, {%0,%1,%2,%3};"                   \
        : "+f"((d)[0]), "+f"((d)[1]), "+f"((d)[2]), "+f"((d)[3])                  \
        : "r"((a)[0]), "r"((a)[1]), "r"((a)[2]), "r"((a)[3]), "r"(b0), "r"(b1))

// ---------------------------------------------------------------------------
// GEMM A (R4-proven): packed split-bf16 both operands, 3-MMA emulation.
// D[M,N] = A[M,K] * B[N,K]^T. CTA 128x256, BK=32, 8 warps, 3-stage cp.async.
// MODE: 0 = fp32 out; 1 = packed bf16-split out + bias[col];
//       2 = fp16 single-plane out + bias[row]
// ---------------------------------------------------------------------------
#define BM 128
#define BN 256
#define BK 32
#define A_U32S  (BM * 40)
#define B_U32S  (BN * 40)
#define A_BYTES (A_U32S * 4)
#define BUF_BYTES ((A_U32S + B_U32S) * 4)   // 61440
#define GEMM_SMEM (3 * BUF_BYTES)           // 184320

__device__ __forceinline__ void load_tiles(const uint32_t* __restrict__ Ag, int lda,
                                           const uint32_t* __restrict__ Bg, int ldb,
                                           uint32_t sbase, int tid) {
    #pragma unroll
    for (int i = 0; i < 4; i++) {
        int t = i * 256 + tid;
        int row = t >> 3, q = t & 7;
        cp16(sbase + (uint32_t)(row * 40 + q * 4) * 4, Ag + (size_t)row * lda + q * 4);
    }
    #pragma unroll
    for (int i = 0; i < 8; i++) {
        int t = i * 256 + tid;
        int row = t >> 3, q = t & 7;
        cp16(sbase + A_BYTES + (uint32_t)(row * 40 + q * 4) * 4, Bg + (size_t)row * ldb + q * 4);
    }
}

__device__ __forceinline__ void compute_tile(uint32_t sa, int lane, int wm, int wn,
                                             float (&acc)[4][8][4]) {
    uint32_t sb = sa + A_BYTES;
    #pragma unroll
    for (int ks = 0; ks < 2; ks++) {
        const int kc = ks * 16 + (lane & 3) * 2;
        uint32_t ah[4][4], al[4][4];
        #pragma unroll
        for (int mt = 0; mt < 4; mt++) {
            int r = wm * 64 + mt * 16 + (lane >> 2);
            uint32_t x0, x1, y0, y1, x2, x3, y2, y3;
            LDS64(x0, x1, sa + (uint32_t)(r * 40 + kc) * 4);
            LDS64(y0, y1, sa + (uint32_t)((r + 8) * 40 + kc) * 4);
            LDS64(x2, x3, sa + (uint32_t)(r * 40 + kc + 8) * 4);
            LDS64(y2, y3, sa + (uint32_t)((r + 8) * 40 + kc + 8) * 4);
            ah[mt][0] = __byte_perm(x0, x1, 0x5410); al[mt][0] = __byte_perm(x0, x1, 0x7632);
            ah[mt][1] = __byte_perm(y0, y1, 0x5410); al[mt][1] = __byte_perm(y0, y1, 0x7632);
            ah[mt][2] = __byte_perm(x2, x3, 0x5410); al[mt][2] = __byte_perm(x2, x3, 0x7632);
            ah[mt][3] = __byte_perm(y2, y3, 0x5410); al[mt][3] = __byte_perm(y2, y3, 0x7632);
        }
        #pragma unroll
        for (int nt = 0; nt < 8; nt++) {
            int r = wn * 64 + nt * 8 + (lane >> 2);
            uint32_t u0, u1, u2, u3;
            LDS64(u0, u1, sb + (uint32_t)(r * 40 + kc) * 4);
            LDS64(u2, u3, sb + (uint32_t)(r * 40 + kc + 8) * 4);
            uint32_t bh0 = __byte_perm(u0, u1, 0x5410), bh1 = __byte_perm(u2, u3, 0x5410);
            uint32_t bl0 = __byte_perm(u0, u1, 0x7632), bl1 = __byte_perm(u2, u3, 0x7632);
            #pragma unroll
            for (int mt = 0; mt < 4; mt++) {
                MMAB(acc[mt][nt], ah[mt], bh0, bh1);
                MMAB(acc[mt][nt], ah[mt], bl0, bl1);
                MMAB(acc[mt][nt], al[mt], bh0, bh1);
            }
        }
    }
}

template<int MODE>
__global__ __launch_bounds__(256)
void gemm_kernel(const uint32_t* __restrict__ A, int lda, size_t sA,
                 const uint32_t* __restrict__ B, int ldb, size_t sB,
                 void* __restrict__ Dv, int ldd, size_t sD,
                 const float* __restrict__ bias, int K)
{
    extern __shared__ __align__(16) uint32_t smraw[];
    const uint32_t smbase = smem_u32(smraw);
    const int tid = threadIdx.x;
    const int lane = tid & 31, wid = tid >> 5;
    const int wm = wid >> 2, wn = wid & 3;
    const int z = blockIdx.z;
    const int bm = blockIdx.y * BM, bn = blockIdx.x * BN;

    A += (size_t)z * sA + (size_t)bm * lda;
    B += (size_t)z * sB + (size_t)bn * ldb;

    float acc[4][8][4];
    #pragma unroll
    for (int i = 0; i < 4; i++)
        #pragma unroll
        for (int j = 0; j < 8; j++)
            #pragma unroll
            for (int v = 0; v < 4; v++) acc[i][j][v] = 0.f;

    const int S = K / BK;
    load_tiles(A, lda, B, ldb, smbase, tid);
    CP_COMMIT();
    load_tiles(A + BK, lda, B + BK, ldb, smbase + BUF_BYTES, tid);
    CP_COMMIT();

    #pragma unroll 1
    for (int s = 0; s < S; s++) {
        CP_WAIT1();
        __syncthreads();
        if (s + 2 < S)
            load_tiles(A + (s + 2) * BK, lda, B + (s + 2) * BK, ldb,
                       smbase + (uint32_t)((s + 2) % 3) * BUF_BYTES, tid);
        CP_COMMIT();
        compute_tile(smbase + (uint32_t)(s % 3) * BUF_BYTES, lane, wm, wn, acc);
    }

    #pragma unroll
    for (int nt = 0; nt < 8; nt++) {
        int col = bn + wn * 64 + nt * 8 + (lane & 3) * 2;
        float bc0 = 0.f, bc1 = 0.f;
        if (MODE == 1) { bc0 = bias[col]; bc1 = bias[col + 1]; }
        #pragma unroll
        for (int mt = 0; mt < 4; mt++) {
            int r0 = bm + wm * 64 + mt * 16 + (lane >> 2);
            if (MODE == 0) {
                float* D = (float*)Dv + (size_t)z * sD;
                *(float2*)&D[(size_t)r0 * ldd + col] =
                    make_float2(acc[mt][nt][0], acc[mt][nt][1]);
                *(float2*)&D[(size_t)(r0 + 8) * ldd + col] =
                    make_float2(acc[mt][nt][2], acc[mt][nt][3]);
            } else if (MODE == 1) {
                uint32_t* D = (uint32_t*)Dv + (size_t)z * sD;
                uint32_t p0 = pack_split(acc[mt][nt][0] + bc0);
                uint32_t p1 = pack_split(acc[mt][nt][1] + bc1);
                uint32_t p2 = pack_split(acc[mt][nt][2] + bc0);
                uint32_t p3 = pack_split(acc[mt][nt][3] + bc1);
                *(uint2*)&D[(size_t)r0 * ldd + col] = make_uint2(p0, p1);
                *(uint2*)&D[(size_t)(r0 + 8) * ldd + col] = make_uint2(p2, p3);
            } else {
                // fp16 single-plane out + bias[row]
                __half* D = (__half*)Dv + (size_t)z * sD;
                float b0 = bias[r0], b8 = bias[r0 + 8];
                __half2 v01 = __floats2half2_rn(acc[mt][nt][0] + b0, acc[mt][nt][1] + b0);
                __half2 v23 = __floats2half2_rn(acc[mt][nt][2] + b8, acc[mt][nt][3] + b8);
                *(__half2*)&D[(size_t)r0 * ldd + col] = v01;
                *(__half2*)&D[(size_t)(r0 + 8) * ldd + col] = v23;
            }
        }
    }
}

// ---------------------------------------------------------------------------
// AV GEMM: A = V fp16 single plane [c][j], B = attn fp16 [i][j].
// D[c][i] fp32. SINGLE MMA per (mt,nt) per k16. CTA 128x256, BK=32, 3-stage.
// Smem rows: 32 halves (64B), stride 40 halves (80B) — LDS32 conflict-free.
// ---------------------------------------------------------------------------
#define OA_BYTES  (BM * 40 * 2)             // 10240
#define OB_BYTES  (BN * 40 * 2)             // 20480
#define OBUF_BYTES (OA_BYTES + OB_BYTES)    // 30720
#define OUT_SMEM  (3 * OBUF_BYTES)          // 92160

__device__ __forceinline__ void load_tiles_av(const __half* __restrict__ Ag,
                                              const __half* __restrict__ Bg,
                                              uint32_t sbase, int tid) {
    #pragma unroll
    for (int i = 0; i < 2; i++) {
        int t = i * 256 + tid;              // 512 tasks: A 128 rows x 4 cp16
        int row = t >> 2, q = t & 3;
        cp16(sbase + (uint32_t)(row * 80 + q * 16), Ag + (size_t)row * NPIX + q * 8);
    }
    #pragma unroll
    for (int i = 0; i < 4; i++) {
        int t = i * 256 + tid;              // 1024 tasks: B 256 rows x 4 cp16
        int row = t >> 2, q = t & 3;
        cp16(sbase + OA_BYTES + (uint32_t)(row * 80 + q * 16), Bg + (size_t)row * NPIX + q * 8);
    }
}

__global__ __launch_bounds__(256)
void av_gemm_kernel(const __half* __restrict__ A,   // g_vh
                    const __half* __restrict__ B,    // g_ah
                    float* __restrict__ D)           // out
{
    extern __shared__ __align__(16) uint32_t smraw[];
    const uint32_t smbase = smem_u32(smraw);
    const int tid = threadIdx.x;
    const int lane = tid & 31, wid = tid >> 5;
    const int wm = wid >> 2, wn = wid & 3;
    const int z = blockIdx.z;
    const int bm = blockIdx.y * BM, bn = blockIdx.x * BN;

    A += (size_t)z * CH * NPIX + (size_t)bm * NPIX;
    B += (size_t)z * NPIX * NPIX + (size_t)bn * NPIX;
    D += (size_t)z * CH * NPIX;

    float acc[4][8][4];
    #pragma unroll
    for (int i = 0; i < 4; i++)
        #pragma unroll
        for (int j = 0; j < 8; j++)
            #pragma unroll
            for (int v = 0; v < 4; v++) acc[i][j][v] = 0.f;

    const int S = NPIX / BK;   // 128
    load_tiles_av(A, B, smbase, tid);
    CP_COMMIT();
    load_tiles_av(A + BK, B + BK, smbase + OBUF_BYTES, tid);
    CP_COMMIT();

    const int qrow = lane >> 2, qcol = lane & 3;

    #pragma unroll 1
    for (int s = 0; s < S; s++) {
        CP_WAIT1();
        __syncthreads();
        if (s + 2 < S)
            load_tiles_av(A + (s + 2) * BK, B + (s + 2) * BK,
                          smbase + (uint32_t)((s + 2) % 3) * OBUF_BYTES, tid);
        CP_COMMIT();

        uint32_t sa = smbase + (uint32_t)(s % 3) * OBUF_BYTES;
        uint32_t sb = sa + OA_BYTES;
        #pragma unroll
        for (int ks = 0; ks < 2; ks++) {
            const int kc = ks * 16 + qcol * 2;     // half col within tile
            uint32_t af[4][4];
            #pragma unroll
            for (int mt = 0; mt < 4; mt++) {
                int r = wm * 64 + mt * 16 + qrow;
                LDS32(af[mt][0], sa + (uint32_t)(r * 80 + kc * 2));
                LDS32(af[mt][1], sa + (uint32_t)((r + 8) * 80 + kc * 2));
                LDS32(af[mt][2], sa + (uint32_t)(r * 80 + (kc + 8) * 2));
                LDS32(af[mt][3], sa + (uint32_t)((r + 8) * 80 + (kc + 8) * 2));
            }
            #pragma unroll
            for (int nt = 0; nt < 8; nt++) {
                int cr = wn * 64 + nt * 8 + qrow;
                uint32_t b0, b1;
                LDS32(b0, sb + (uint32_t)(cr * 80 + kc * 2));
                LDS32(b1, sb + (uint32_t)(cr * 80 + (kc + 8) * 2));
                #pragma unroll
                for (int mt = 0; mt < 4; mt++)
                    MMAH(acc[mt][nt], af[mt], b0, b1);
            }
        }
    }

    #pragma unroll
    for (int nt = 0; nt < 8; nt++) {
        int col = bn + wn * 64 + nt * 8 + qcol * 2;
        #pragma unroll
        for (int mt = 0; mt < 4; mt++) {
            int r0 = bm + wm * 64 + mt * 16 + qrow;
            *(float2*)&D[(size_t)r0 * NPIX + col] =
                make_float2(acc[mt][nt][0], acc[mt][nt][1]);
            *(float2*)&D[(size_t)(r0 + 8) * NPIX + col] =
                make_float2(acc[mt][nt][2], acc[mt][nt][3]);
        }
    }
}

// ---------------------------------------------------------------------------
// Packing kernels
// ---------------------------------------------------------------------------
__global__ __launch_bounds__(256) void pack_w_kernel(
    const float* __restrict__ wq, const float* __restrict__ wk,
    const float* __restrict__ wv)
{
    int i = blockIdx.x * 256 + threadIdx.x;
    g_wp[i]               = pack_split(wq[i]);
    g_wp[CH * CH + i]     = pack_split(wk[i]);
    g_wp[2 * CH * CH + i] = pack_split(wv[i]);
}

__global__ __launch_bounds__(256) void pack_xt_kernel(const float* __restrict__ x)
{
    __shared__ float t[32][33];
    const int b = blockIdx.z;
    const int n0 = blockIdx.x * 32, c0 = blockIdx.y * 32;
    const int tx = threadIdx.x, ty = threadIdx.y;   // 32 x 8
    const float* xb = x + (size_t)b * CH * NPIX;
    #pragma unroll
    for (int i = 0; i < 4; i++)
        t[ty * 4 + i][tx] = xb[(size_t)(c0 + ty * 4 + i) * NPIX + n0 + tx];
    __syncthreads();
    uint32_t* xt = g_xt + (size_t)b * NPIX * CH;
    #pragma unroll
    for (int i = 0; i < 4; i++)
        xt[(size_t)(n0 + ty * 4 + i) * CH + c0 + tx] = pack_split(t[tx][ty * 4 + i]);
}

// ---------------------------------------------------------------------------
// Softmax: fp32 scores -> fp16 attn
// ---------------------------------------------------------------------------
__global__ __launch_bounds__(256) void softmax_kernel()
{
    const float* row = g_s + (size_t)blockIdx.x * NPIX;
    __half* orow = g_ah + (size_t)blockIdx.x * NPIX;
    const int tid = threadIdx.x;

    float v[16];
    float mx = -1e30f;
    #pragma unroll
    for (int i = 0; i < 16; i++) {
        v[i] = row[tid + 256 * i];
        mx = fmaxf(mx, v[i]);
    }
    __shared__ float red[8];
    #pragma unroll
    for (int o = 16; o > 0; o >>= 1)
        mx = fmaxf(mx, __shfl_xor_sync(0xffffffffu, mx, o));
    if ((tid & 31) == 0) red[tid >> 5] = mx;
    __syncthreads();
    float bm = red[0];
    #pragma unroll
    for (int i = 1; i < 8; i++) bm = fmaxf(bm, red[i]);
    __syncthreads();

    float sum = 0.f;
    #pragma unroll
    for (int i = 0; i < 16; i++) {
        v[i] = expf(v[i] - bm);
        sum += v[i];
    }
    #pragma unroll
    for (int o = 16; o > 0; o >>= 1)
        sum += __shfl_xor_sync(0xffffffffu, sum, o);
    if ((tid & 31) == 0) red[tid >> 5] = sum;
    __syncthreads();
    float tot = 0.f;
    #pragma unroll
    for (int i = 0; i < 8; i++) tot += red[i];
    float inv = 1.0f / tot;

    #pragma unroll
    for (int i = 0; i < 16; i++)
        orow[tid + 256 * i] = __float2half(v[i] * inv);
}

// ---------------------------------------------------------------------------
extern "C" void kernel_launch(void* const* d_in, const int* in_sizes, int n_in,
                              void* d_out, int out_size)
{
    const float* x  = (const float*)d_in[0];
    const float* wq = (const float*)d_in[1];
    const float* bq = (const float*)d_in[2];
    const float* wk = (const float*)d_in[3];
    const float* bk = (const float*)d_in[4];
    const float* wv = (const float*)d_in[5];
    const float* bv = (const float*)d_in[6];
    float* out = (float*)d_out;

    void *pwp, *pxt, *pqt, *pkt, *pvh, *ps, *pah;
    cudaGetSymbolAddress(&pwp, g_wp);
    cudaGetSymbolAddress(&pxt, g_xt);
    cudaGetSymbolAddress(&pqt, g_qt);
    cudaGetSymbolAddress(&pkt, g_kt);
    cudaGetSymbolAddress(&pvh, g_vh);
    cudaGetSymbolAddress(&ps,  g_s);
    cudaGetSymbolAddress(&pah, g_ah);
    uint32_t* wp = (uint32_t*)pwp;
    uint32_t* xt = (uint32_t*)pxt;
    uint32_t* qt = (uint32_t*)pqt;
    uint32_t* kt = (uint32_t*)pkt;
    __half*   vh = (__half*)pvh;
    float*    sc = (float*)ps;
    __half*   ah = (__half*)pah;

    cudaFuncSetAttribute(gemm_kernel<0>, cudaFuncAttributeMaxDynamicSharedMemorySize, GEMM_SMEM);
    cudaFuncSetAttribute(gemm_kernel<1>, cudaFuncAttributeMaxDynamicSharedMemorySize, GEMM_SMEM);
    cudaFuncSetAttribute(gemm_kernel<2>, cudaFuncAttributeMaxDynamicSharedMemorySize, GEMM_SMEM);
    cudaFuncSetAttribute(av_gemm_kernel, cudaFuncAttributeMaxDynamicSharedMemorySize, OUT_SMEM);

    pack_w_kernel<<<CH * CH / 256, 256>>>(wq, wk, wv);
    pack_xt_kernel<<<dim3(NPIX / 32, CH / 32, BATCH), dim3(32, 8)>>>(x);

    // Q^T[n][c] = X^T[n][k] * Wq[c][k]^T + bq (col bias)
    gemm_kernel<1><<<dim3(1, 32, BATCH), 256, GEMM_SMEM>>>(
        xt, CH, (size_t)NPIX * CH, wp, CH, 0,
        qt, CH, (size_t)NPIX * CH, bq, CH);
    gemm_kernel<1><<<dim3(1, 32, BATCH), 256, GEMM_SMEM>>>(
        xt, CH, (size_t)NPIX * CH, wp + CH * CH, CH, 0,
        kt, CH, (size_t)NPIX * CH, bk, CH);
    // V[c][n] = Wv[c][k] * X^T[n][k]^T + bv (row bias) -> fp16 single plane
    gemm_kernel<2><<<dim3(NPIX / BN, CH / BM, BATCH), 256, GEMM_SMEM>>>(
        wp + 2 * CH * CH, CH, 0, xt, CH, (size_t)NPIX * CH,
        vh, NPIX, (size_t)CH * NPIX, bv, CH);
    // scores[i][j] = Q^T[i][k] * K^T[j][k]^T
    gemm_kernel<0><<<dim3(NPIX / BN, NPIX / BM, BATCH), 256, GEMM_SMEM>>>(
        qt, CH, (size_t)NPIX * CH, kt, CH, (size_t)NPIX * CH,
        sc, NPIX, (size_t)NPIX * NPIX, nullptr, CH);
    softmax_kernel<<<BATCH * NPIX, 256>>>();
    // out[c][i] = V[c][j] * attn[i][j]^T
    av_gemm_kernel<<<dim3(NPIX / BN, CH / BM, BATCH), 256, OUT_SMEM>>>(vh, ah, out);
}

// round 10
// speedup vs baseline: 1.4681x; 1.0343x over previous
#include <cuda_runtime.h>
#include <cuda_bf16.h>
#include <cuda_fp16.h>
#include <math.h>
#include <stdint.h>

#define BATCH 8
#define CH    256
#define NPIX  4096

// Packed split formats: u32 = lo16(hi) | lo16(lo)<<16, value ~= hi + lo
static __device__ uint32_t g_wp[3 * CH * CH];                  // packed bf16 wq|wk|wv
static __device__ uint32_t g_xt[(size_t)BATCH * NPIX * CH];    // x^T  [b][n][c] bf16-split
static __device__ uint32_t g_qt[(size_t)BATCH * NPIX * CH];    // Q^T  [b][n][c] bf16-split
static __device__ uint32_t g_kt[(size_t)BATCH * NPIX * CH];    // K^T  [b][n][c] bf16-split
static __device__ __half   g_vh[(size_t)BATCH * CH * NPIX];    // V    [b][c][n] fp16 single
static __device__ float    g_s [(size_t)BATCH * NPIX * NPIX];  // scores fp32
static __device__ __half   g_ah[(size_t)BATCH * NPIX * NPIX];  // attn fp16 [b][i][j]

__device__ __forceinline__ uint32_t smem_u32(const void* p) {
    uint32_t a;
    asm("{ .reg .u64 t; cvta.to.shared.u64 t, %1; cvt.u32.u64 %0, t; }" : "=r"(a) : "l"(p));
    return a;
}
__device__ __forceinline__ uint32_t pack_split(float v) {         // bf16 hi+lo
    __nv_bfloat16 h = __float2bfloat16(v);
    float r = v - __bfloat162float(h);
    __nv_bfloat16 l = __float2bfloat16(r);
    return (uint32_t)__bfloat16_as_ushort(h) | ((uint32_t)__bfloat16_as_ushort(l) << 16);
}
__device__ __forceinline__ void cp16(uint32_t saddr, const void* g) {
    uint64_t ga;
    asm("cvta.to.global.u64 %0, %1;" : "=l"(ga) : "l"(g));
    asm volatile("cp.async.cg.shared.global [%0], [%1], 16;" :: "r"(saddr), "l"(ga));
}
#define CP_COMMIT() asm volatile("cp.async.commit_group;" ::: "memory")
#define CP_WAIT1()  asm volatile("cp.async.wait_group 1;"  ::: "memory")
#define CP_WAIT0()  asm volatile("cp.async.wait_group 0;"  ::: "memory")
#define LDS64(a, b, addr) \
    asm volatile("ld.shared.v2.u32 {%0,%1}, [%2];" : "=r"(a), "=r"(b) : "r"(addr))
#define LDS32(a, addr) \
    asm volatile("ld.shared.u32 %0, [%1];" : "=r"(a) : "r"(addr))
#define MMAB(d, a, b0, b1)                                                        \
    asm volatile("mma.sync.aligned.m16n8k16.row.col.f32.bf16.bf16.f32 "           \
        "{%0,%1,%2,%3}, {%4,%5,%6,%7}, {%8,%9}, {%0,%1,%2,%3};"                   \
        : "+f"((d)[0]), "+f"((d)[1]), "+f"((d)[2]), "+f"((d)[3])                  \
        : "r"((a)[0]), "r"((a)[1]), "r"((a)[2]), "r"((a)[3]), "r"(b0), "r"(b1))
#define MMAH(d, a, b0, b1)                                                        \
    asm volatile("mma.sync.aligned.m16n8k16.row.col.f32.f16.f16.f32 "             \
        "{%0,%1,%2,%3}, {%4,%5,%6,%7}, {%8,%9}, {%0,%1,%2,%3};"                   \
        : "+f"((d)[0]), "+f"((d)[1]), "+f"((d)[2]), "+f"((d)[3])                  \
        : "r"((a)[0]), "r"((a)[1]), "r"((a)[2]), "r"((a)[3]), "r"(b0), "r"(b1))

// ---------------------------------------------------------------------------
// QKV GEMM (R4/R9-proven): packed split-bf16, 3-MMA. CTA 128x256, 1 CTA/SM.
// MODE: 1 = packed bf16-split out + bias[col]; 2 = fp16 single out + bias[row]
// ---------------------------------------------------------------------------
#define BM 128
#define BN 256
#define BK 32
#define A_U32S  (BM * 40)
#define B_U32S  (BN * 40)
#define A_BYTES (A_U32S * 4)
#define BUF_BYTES ((A_U32S + B_U32S) * 4)   // 61440
#define GEMM_SMEM (3 * BUF_BYTES)           // 184320

__device__ __forceinline__ void load_tiles(const uint32_t* __restrict__ Ag, int lda,
                                           const uint32_t* __restrict__ Bg, int ldb,
                                           uint32_t sbase, int tid) {
    #pragma unroll
    for (int i = 0; i < 4; i++) {
        int t = i * 256 + tid;
        int row = t >> 3, q = t & 7;
        cp16(sbase + (uint32_t)(row * 40 + q * 4) * 4, Ag + (size_t)row * lda + q * 4);
    }
    #pragma unroll
    for (int i = 0; i < 8; i++) {
        int t = i * 256 + tid;
        int row = t >> 3, q = t & 7;
        cp16(sbase + A_BYTES + (uint32_t)(row * 40 + q * 4) * 4, Bg + (size_t)row * ldb + q * 4);
    }
}

__device__ __forceinline__ void compute_tile(uint32_t sa, int lane, int wm, int wn,
                                             float (&acc)[4][8][4]) {
    uint32_t sb = sa + A_BYTES;
    #pragma unroll
    for (int ks = 0; ks < 2; ks++) {
        const int kc = ks * 16 + (lane & 3) * 2;
        uint32_t ah[4][4], al[4][4];
        #pragma unroll
        for (int mt = 0; mt < 4; mt++) {
            int r = wm * 64 + mt * 16 + (lane >> 2);
            uint32_t x0, x1, y0, y1, x2, x3, y2, y3;
            LDS64(x0, x1, sa + (uint32_t)(r * 40 + kc) * 4);
            LDS64(y0, y1, sa + (uint32_t)((r + 8) * 40 + kc) * 4);
            LDS64(x2, x3, sa + (uint32_t)(r * 40 + kc + 8) * 4);
            LDS64(y2, y3, sa + (uint32_t)((r + 8) * 40 + kc + 8) * 4);
            ah[mt][0] = __byte_perm(x0, x1, 0x5410); al[mt][0] = __byte_perm(x0, x1, 0x7632);
            ah[mt][1] = __byte_perm(y0, y1, 0x5410); al[mt][1] = __byte_perm(y0, y1, 0x7632);
            ah[mt][2] = __byte_perm(x2, x3, 0x5410); al[mt][2] = __byte_perm(x2, x3, 0x7632);
            ah[mt][3] = __byte_perm(y2, y3, 0x5410); al[mt][3] = __byte_perm(y2, y3, 0x7632);
        }
        #pragma unroll
        for (int nt = 0; nt < 8; nt++) {
            int r = wn * 64 + nt * 8 + (lane >> 2);
            uint32_t u0, u1, u2, u3;
            LDS64(u0, u1, sb + (uint32_t)(r * 40 + kc) * 4);
            LDS64(u2, u3, sb + (uint32_t)(r * 40 + kc + 8) * 4);
            uint32_t bh0 = __byte_perm(u0, u1, 0x5410), bh1 = __byte_perm(u2, u3, 0x5410);
            uint32_t bl0 = __byte_perm(u0, u1, 0x7632), bl1 = __byte_perm(u2, u3, 0x7632);
            #pragma unroll
            for (int mt = 0; mt < 4; mt++) {
                MMAB(acc[mt][nt], ah[mt], bh0, bh1);
                MMAB(acc[mt][nt], ah[mt], bl0, bl1);
                MMAB(acc[mt][nt], al[mt], bh0, bh1);
            }
        }
    }
}

template<int MODE>
__global__ __launch_bounds__(256)
void gemm_kernel(const uint32_t* __restrict__ A, int lda, size_t sA,
                 const uint32_t* __restrict__ B, int ldb, size_t sB,
                 void* __restrict__ Dv, int ldd, size_t sD,
                 const float* __restrict__ bias, int K)
{
    extern __shared__ __align__(16) uint32_t smraw[];
    const uint32_t smbase = smem_u32(smraw);
    const int tid = threadIdx.x;
    const int lane = tid & 31, wid = tid >> 5;
    const int wm = wid >> 2, wn = wid & 3;
    const int z = blockIdx.z;
    const int bm = blockIdx.y * BM, bn = blockIdx.x * BN;

    A += (size_t)z * sA + (size_t)bm * lda;
    B += (size_t)z * sB + (size_t)bn * ldb;

    float acc[4][8][4];
    #pragma unroll
    for (int i = 0; i < 4; i++)
        #pragma unroll
        for (int j = 0; j < 8; j++)
            #pragma unroll
            for (int v = 0; v < 4; v++) acc[i][j][v] = 0.f;

    const int S = K / BK;
    load_tiles(A, lda, B, ldb, smbase, tid);
    CP_COMMIT();
    load_tiles(A + BK, lda, B + BK, ldb, smbase + BUF_BYTES, tid);
    CP_COMMIT();

    #pragma unroll 1
    for (int s = 0; s < S; s++) {
        CP_WAIT1();
        __syncthreads();
        if (s + 2 < S)
            load_tiles(A + (s + 2) * BK, lda, B + (s + 2) * BK, ldb,
                       smbase + (uint32_t)((s + 2) % 3) * BUF_BYTES, tid);
        CP_COMMIT();
        compute_tile(smbase + (uint32_t)(s % 3) * BUF_BYTES, lane, wm, wn, acc);
    }

    #pragma unroll
    for (int nt = 0; nt < 8; nt++) {
        int col = bn + wn * 64 + nt * 8 + (lane & 3) * 2;
        float bc0 = 0.f, bc1 = 0.f;
        if (MODE == 1) { bc0 = bias[col]; bc1 = bias[col + 1]; }
        #pragma unroll
        for (int mt = 0; mt < 4; mt++) {
            int r0 = bm + wm * 64 + mt * 16 + (lane >> 2);
            if (MODE == 1) {
                uint32_t* D = (uint32_t*)Dv + (size_t)z * sD;
                uint32_t p0 = pack_split(acc[mt][nt][0] + bc0);
                uint32_t p1 = pack_split(acc[mt][nt][1] + bc1);
                uint32_t p2 = pack_split(acc[mt][nt][2] + bc0);
                uint32_t p3 = pack_split(acc[mt][nt][3] + bc1);
                *(uint2*)&D[(size_t)r0 * ldd + col] = make_uint2(p0, p1);
                *(uint2*)&D[(size_t)(r0 + 8) * ldd + col] = make_uint2(p2, p3);
            } else {
                __half* D = (__half*)Dv + (size_t)z * sD;
                float b0 = bias[r0], b8 = bias[r0 + 8];
                __half2 v01 = __floats2half2_rn(acc[mt][nt][0] + b0, acc[mt][nt][1] + b0);
                __half2 v23 = __floats2half2_rn(acc[mt][nt][2] + b8, acc[mt][nt][3] + b8);
                *(__half2*)&D[(size_t)r0 * ldd + col] = v01;
                *(__half2*)&D[(size_t)(r0 + 8) * ldd + col] = v23;
            }
        }
    }
}

// ---------------------------------------------------------------------------
// Scores GEMM, 2 CTAs/SM: CTA 128x128, warp tile 64x32, acc 64 regs.
// 2-stage cp.async (80 KB smem/CTA). D[i][j] fp32.
// ---------------------------------------------------------------------------
#define S2TILE 20480                        // 128 rows * 40 u32 * 4B
#define S2BUF  (2 * S2TILE)                 // 40960
#define S2SMEM (2 * S2BUF)                  // 81920

__device__ __forceinline__ void load_s2(const uint32_t* __restrict__ Ag,
                                        const uint32_t* __restrict__ Bg,
                                        uint32_t sbase, int tid) {
    #pragma unroll
    for (int i = 0; i < 4; i++) {
        int t = i * 256 + tid;
        int row = t >> 3, q = t & 7;
        cp16(sbase + (uint32_t)(row * 40 + q * 4) * 4, Ag + (size_t)row * CH + q * 4);
    }
    #pragma unroll
    for (int i = 0; i < 4; i++) {
        int t = i * 256 + tid;
        int row = t >> 3, q = t & 7;
        cp16(sbase + S2TILE + (uint32_t)(row * 40 + q * 4) * 4, Bg + (size_t)row * CH + q * 4);
    }
}

__global__ __launch_bounds__(256, 2)
void scores2_kernel()
{
    extern __shared__ __align__(16) uint32_t smraw[];
    const uint32_t smbase = smem_u32(smraw);
    const int tid = threadIdx.x;
    const int lane = tid & 31, wid = tid >> 5;
    const int wm = wid >> 2, wn = wid & 3;    // wm 0..1 (64 rows), wn 0..3 (32 cols)
    const int z = blockIdx.z;
    const int bm = blockIdx.y * 128, bn = blockIdx.x * 128;

    const uint32_t* A = g_qt + (size_t)z * NPIX * CH + (size_t)bm * CH;
    const uint32_t* B = g_kt + (size_t)z * NPIX * CH + (size_t)bn * CH;

    float acc[4][4][4];
    #pragma unroll
    for (int i = 0; i < 4; i++)
        #pragma unroll
        for (int j = 0; j < 4; j++)
            #pragma unroll
            for (int v = 0; v < 4; v++) acc[i][j][v] = 0.f;

    const int qrow = lane >> 2, qcol = lane & 3;
    const int S = CH / BK;   // 8

    load_s2(A, B, smbase, tid);
    CP_COMMIT();

    #pragma unroll 1
    for (int s = 0; s < S; s++) {
        __syncthreads();      // all warps done with compute(s-1) (buffer reuse)
        if (s + 1 < S) {
            load_s2(A + (s + 1) * BK, B + (s + 1) * BK,
                    smbase + (uint32_t)((s + 1) & 1) * S2BUF, tid);
            CP_COMMIT();
            CP_WAIT1();
        } else {
            CP_WAIT0();
        }
        __syncthreads();      // load(s) visible to all
        uint32_t sa = smbase + (uint32_t)(s & 1) * S2BUF;
        uint32_t sb = sa + S2TILE;
        #pragma unroll
        for (int ks = 0; ks < 2; ks++) {
            const int kc = ks * 16 + qcol * 2;
            uint32_t ah[4][4], al[4][4];
            #pragma unroll
            for (int mt = 0; mt < 4; mt++) {
                int r = wm * 64 + mt * 16 + qrow;
                uint32_t x0, x1, y0, y1, x2, x3, y2, y3;
                LDS64(x0, x1, sa + (uint32_t)(r * 40 + kc) * 4);
                LDS64(y0, y1, sa + (uint32_t)((r + 8) * 40 + kc) * 4);
                LDS64(x2, x3, sa + (uint32_t)(r * 40 + kc + 8) * 4);
                LDS64(y2, y3, sa + (uint32_t)((r + 8) * 40 + kc + 8) * 4);
                ah[mt][0] = __byte_perm(x0, x1, 0x5410); al[mt][0] = __byte_perm(x0, x1, 0x7632);
                ah[mt][1] = __byte_perm(y0, y1, 0x5410); al[mt][1] = __byte_perm(y0, y1, 0x7632);
                ah[mt][2] = __byte_perm(x2, x3, 0x5410); al[mt][2] = __byte_perm(x2, x3, 0x7632);
                ah[mt][3] = __byte_perm(y2, y3, 0x5410); al[mt][3] = __byte_perm(y2, y3, 0x7632);
            }
            #pragma unroll
            for (int nt = 0; nt < 4; nt++) {
                int r = wn * 32 + nt * 8 + qrow;
                uint32_t u0, u1, u2, u3;
                LDS64(u0, u1, sb + (uint32_t)(r * 40 + kc) * 4);
                LDS64(u2, u3, sb + (uint32_t)(r * 40 + kc + 8) * 4);
                uint32_t bh0 = __byte_perm(u0, u1, 0x5410), bh1 = __byte_perm(u2, u3, 0x5410);
                uint32_t bl0 = __byte_perm(u0, u1, 0x7632), bl1 = __byte_perm(u2, u3, 0x7632);
                #pragma unroll
                for (int mt = 0; mt < 4; mt++) {
                    MMAB(acc[mt][nt], ah[mt], bh0, bh1);
                    MMAB(acc[mt][nt], ah[mt], bl0, bl1);
                    MMAB(acc[mt][nt], al[mt], bh0, bh1);
                }
            }
        }
    }

    float* D = g_s + (size_t)z * NPIX * NPIX;
    #pragma unroll
    for (int nt = 0; nt < 4; nt++) {
        int col = bn + wn * 32 + nt * 8 + qcol * 2;
        #pragma unroll
        for (int mt = 0; mt < 4; mt++) {
            int r0 = bm + wm * 64 + mt * 16 + qrow;
            *(float2*)&D[(size_t)r0 * NPIX + col] =
                make_float2(acc[mt][nt][0], acc[mt][nt][1]);
            *(float2*)&D[(size_t)(r0 + 8) * NPIX + col] =
                make_float2(acc[mt][nt][2], acc[mt][nt][3]);
        }
    }
}

// ---------------------------------------------------------------------------
// AV GEMM, 2 CTAs/SM: CTA 128(c)x128(i), warp tile 64x32, 1 fp16 MMA/pair.
// 3-stage cp.async (60 KB smem/CTA). D[c][i] fp32.
// ---------------------------------------------------------------------------
#define AVTILE 10240                        // 128 rows * 40 halves * 2B
#define AVBUF  (2 * AVTILE)                 // 20480
#define AVSMEM (3 * AVBUF)                  // 61440

__device__ __forceinline__ void load_av2(const __half* __restrict__ Ag,
                                         const __half* __restrict__ Bg,
                                         uint32_t sbase, int tid) {
    #pragma unroll
    for (int i = 0; i < 2; i++) {
        int t = i * 256 + tid;
        int row = t >> 2, q = t & 3;
        cp16(sbase + (uint32_t)(row * 80 + q * 16), Ag + (size_t)row * NPIX + q * 8);
    }
    #pragma unroll
    for (int i = 0; i < 2; i++) {
        int t = i * 256 + tid;
        int row = t >> 2, q = t & 3;
        cp16(sbase + AVTILE + (uint32_t)(row * 80 + q * 16), Bg + (size_t)row * NPIX + q * 8);
    }
}

__global__ __launch_bounds__(256, 2)
void av2_kernel(const __half* __restrict__ A,   // g_vh
                const __half* __restrict__ B,    // g_ah
                float* __restrict__ D)           // out
{
    extern __shared__ __align__(16) uint32_t smraw[];
    const uint32_t smbase = smem_u32(smraw);
    const int tid = threadIdx.x;
    const int lane = tid & 31, wid = tid >> 5;
    const int wm = wid >> 2, wn = wid & 3;
    const int z = blockIdx.z;
    const int bm = blockIdx.y * 128, bn = blockIdx.x * 128;

    A += (size_t)z * CH * NPIX + (size_t)bm * NPIX;
    B += (size_t)z * NPIX * NPIX + (size_t)bn * NPIX;
    D += (size_t)z * CH * NPIX;

    float acc[4][4][4];
    #pragma unroll
    for (int i = 0; i < 4; i++)
        #pragma unroll
        for (int j = 0; j < 4; j++)
            #pragma unroll
            for (int v = 0; v < 4; v++) acc[i][j][v] = 0.f;

    const int qrow = lane >> 2, qcol = lane & 3;
    const int S = NPIX / BK;   // 128

    load_av2(A, B, smbase, tid);
    CP_COMMIT();
    load_av2(A + BK, B + BK, smbase + AVBUF, tid);
    CP_COMMIT();

    #pragma unroll 1
    for (int s = 0; s < S; s++) {
        CP_WAIT1();
        __syncthreads();
        if (s + 2 < S)
            load_av2(A + (s + 2) * BK, B + (s + 2) * BK,
                     smbase + (uint32_t)((s + 2) % 3) * AVBUF, tid);
        CP_COMMIT();

        uint32_t sa = smbase + (uint32_t)(s % 3) * AVBUF;
        uint32_t sb = sa + AVTILE;
        #pragma unroll
        for (int ks = 0; ks < 2; ks++) {
            const int kc = ks * 16 + qcol * 2;     // half col within tile
            uint32_t af[4][4];
            #pragma unroll
            for (int mt = 0; mt < 4; mt++) {
                int r = wm * 64 + mt * 16 + qrow;
                LDS32(af[mt][0], sa + (uint32_t)(r * 80 + kc * 2));
                LDS32(af[mt][1], sa + (uint32_t)((r + 8) * 80 + kc * 2));
                LDS32(af[mt][2], sa + (uint32_t)(r * 80 + (kc + 8) * 2));
                LDS32(af[mt][3], sa + (uint32_t)((r + 8) * 80 + (kc + 8) * 2));
            }
            #pragma unroll
            for (int nt = 0; nt < 4; nt++) {
                int cr = wn * 32 + nt * 8 + qrow;
                uint32_t b0, b1;
                LDS32(b0, sb + (uint32_t)(cr * 80 + kc * 2));
                LDS32(b1, sb + (uint32_t)(cr * 80 + (kc + 8) * 2));
                #pragma unroll
                for (int mt = 0; mt < 4; mt++)
                    MMAH(acc[mt][nt], af[mt], b0, b1);
            }
        }
    }

    #pragma unroll
    for (int nt = 0; nt < 4; nt++) {
        int col = bn + wn * 32 + nt * 8 + qcol * 2;
        #pragma unroll
        for (int mt = 0; mt < 4; mt++) {
            int r0 = bm + wm * 64 + mt * 16 + qrow;
            *(float2*)&D[(size_t)r0 * NPIX + col] =
                make_float2(acc[mt][nt][0], acc[mt][nt][1]);
            *(float2*)&D[(size_t)(r0 + 8) * NPIX + col] =
                make_float2(acc[mt][nt][2], acc[mt][nt][3]);
        }
    }
}

// ---------------------------------------------------------------------------
// Packing kernels
// ---------------------------------------------------------------------------
__global__ __launch_bounds__(256) void pack_w_kernel(
    const float* __restrict__ wq, const float* __restrict__ wk,
    const float* __restrict__ wv)
{
    int i = blockIdx.x * 256 + threadIdx.x;
    g_wp[i]               = pack_split(wq[i]);
    g_wp[CH * CH + i]     = pack_split(wk[i]);
    g_wp[2 * CH * CH + i] = pack_split(wv[i]);
}

__global__ __launch_bounds__(256) void pack_xt_kernel(const float* __restrict__ x)
{
    __shared__ float t[32][33];
    const int b = blockIdx.z;
    const int n0 = blockIdx.x * 32, c0 = blockIdx.y * 32;
    const int tx = threadIdx.x, ty = threadIdx.y;   // 32 x 8
    const float* xb = x + (size_t)b * CH * NPIX;
    #pragma unroll
    for (int i = 0; i < 4; i++)
        t[ty * 4 + i][tx] = xb[(size_t)(c0 + ty * 4 + i) * NPIX + n0 + tx];
    __syncthreads();
    uint32_t* xt = g_xt + (size_t)b * NPIX * CH;
    #pragma unroll
    for (int i = 0; i < 4; i++)
        xt[(size_t)(n0 + ty * 4 + i) * CH + c0 + tx] = pack_split(t[tx][ty * 4 + i]);
}

// ---------------------------------------------------------------------------
// Softmax: fp32 scores -> fp16 attn (memory-bound, at HBM roof)
// ---------------------------------------------------------------------------
__global__ __launch_bounds__(256) void softmax_kernel()
{
    const float* row = g_s + (size_t)blockIdx.x * NPIX;
    __half* orow = g_ah + (size_t)blockIdx.x * NPIX;
    const int tid = threadIdx.x;

    float v[16];
    float mx = -1e30f;
    #pragma unroll
    for (int i = 0; i < 16; i++) {
        v[i] = row[tid + 256 * i];
        mx = fmaxf(mx, v[i]);
    }
    __shared__ float red[8];
    #pragma unroll
    for (int o = 16; o > 0; o >>= 1)
        mx = fmaxf(mx, __shfl_xor_sync(0xffffffffu, mx, o));
    if ((tid & 31) == 0) red[tid >> 5] = mx;
    __syncthreads();
    float bm = red[0];
    #pragma unroll
    for (int i = 1; i < 8; i++) bm = fmaxf(bm, red[i]);
    __syncthreads();

    float sum = 0.f;
    #pragma unroll
    for (int i = 0; i < 16; i++) {
        v[i] = expf(v[i] - bm);
        sum += v[i];
    }
    #pragma unroll
    for (int o = 16; o > 0; o >>= 1)
        sum += __shfl_xor_sync(0xffffffffu, sum, o);
    if ((tid & 31) == 0) red[tid >> 5] = sum;
    __syncthreads();
    float tot = 0.f;
    #pragma unroll
    for (int i = 0; i < 8; i++) tot += red[i];
    float inv = 1.0f / tot;

    #pragma unroll
    for (int i = 0; i < 16; i++)
        orow[tid + 256 * i] = __float2half(v[i] * inv);
}

// ---------------------------------------------------------------------------
extern "C" void kernel_launch(void* const* d_in, const int* in_sizes, int n_in,
                              void* d_out, int out_size)
{
    const float* x  = (const float*)d_in[0];
    const float* wq = (const float*)d_in[1];
    const float* bq = (const float*)d_in[2];
    const float* wk = (const float*)d_in[3];
    const float* bk = (const float*)d_in[4];
    const float* wv = (const float*)d_in[5];
    const float* bv = (const float*)d_in[6];
    float* out = (float*)d_out;

    void *pwp, *pxt, *pqt, *pkt, *pvh;
    cudaGetSymbolAddress(&pwp, g_wp);
    cudaGetSymbolAddress(&pxt, g_xt);
    cudaGetSymbolAddress(&pqt, g_qt);
    cudaGetSymbolAddress(&pkt, g_kt);
    cudaGetSymbolAddress(&pvh, g_vh);
    void *pah;
    cudaGetSymbolAddress(&pah, g_ah);
    uint32_t* wp = (uint32_t*)pwp;
    uint32_t* xt = (uint32_t*)pxt;
    uint32_t* qt = (uint32_t*)pqt;
    uint32_t* kt = (uint32_t*)pkt;
    __half*   vh = (__half*)pvh;
    __half*   ah = (__half*)pah;

    cudaFuncSetAttribute(gemm_kernel<1>, cudaFuncAttributeMaxDynamicSharedMemorySize, GEMM_SMEM);
    cudaFuncSetAttribute(gemm_kernel<2>, cudaFuncAttributeMaxDynamicSharedMemorySize, GEMM_SMEM);
    cudaFuncSetAttribute(scores2_kernel, cudaFuncAttributeMaxDynamicSharedMemorySize, S2SMEM);
    cudaFuncSetAttribute(av2_kernel,     cudaFuncAttributeMaxDynamicSharedMemorySize, AVSMEM);

    pack_w_kernel<<<CH * CH / 256, 256>>>(wq, wk, wv);
    pack_xt_kernel<<<dim3(NPIX / 32, CH / 32, BATCH), dim3(32, 8)>>>(x);

    // Q^T[n][c] = X^T[n][k] * Wq[c][k]^T + bq (col bias)
    gemm_kernel<1><<<dim3(1, 32, BATCH), 256, GEMM_SMEM>>>(
        xt, CH, (size_t)NPIX * CH, wp, CH, 0,
        qt, CH, (size_t)NPIX * CH, bq, CH);
    gemm_kernel<1><<<dim3(1, 32, BATCH), 256, GEMM_SMEM>>>(
        xt, CH, (size_t)NPIX * CH, wp + CH * CH, CH, 0,
        kt, CH, (size_t)NPIX * CH, bk, CH);
    // V[c][n] = Wv[c][k] * X^T[n][k]^T + bv (row bias) -> fp16 single plane
    gemm_kernel<2><<<dim3(NPIX / BN, CH / BM, BATCH), 256, GEMM_SMEM>>>(
        wp + 2 * CH * CH, CH, 0, xt, CH, (size_t)NPIX * CH,
        vh, NPIX, (size_t)CH * NPIX, bv, CH);
    // scores[i][j] = Q^T[i][k] * K^T[j][k]^T   (2 CTAs/SM)
    scores2_kernel<<<dim3(NPIX / 128, NPIX / 128, BATCH), 256, S2SMEM>>>();
    softmax_kernel<<<BATCH * NPIX, 256>>>();
    // out[c][i] = V[c][j] * attn[i][j]^T       (2 CTAs/SM)
    av2_kernel<<<dim3(NPIX / 128, CH / 128, BATCH), 256, AVSMEM>>>(vh, ah, out);
}